// round 10
// baseline (speedup 1.0000x reference)
#include <cuda_runtime.h>
#include <cuda_bf16.h>
#include <cstdint>

// One-hot expansion: mask [1,1,256,256,48] fp32 integer labels 0..40
//   -> out [1,40,256,256,48], out[:,c] = (mask == c+1) ? 1.0f : 0.0f
//
// Streaming-store bound. Plateau at ~5.8 TB/s is invariant to L2 evict
// policy [R6], store MLP [R7], occupancy [R6/R7], stream locality [R8].
// DRAM active is only ~73% => possibly limited by L2 dirty-writeback
// scheduling, not raw DRAM BW. This round: WRITE-THROUGH stores (__stwt)
// so output never accumulates as dirty L2 lines — the one store policy
// not yet tested. Layout is the converged R9 one (thread t <-> float4 t,
// exact grid, no bounds check).

#define N_LABELS 40

__global__ __launch_bounds__(256)
void onehot40_kernel(const float4* __restrict__ mask4,
                     float4* __restrict__ out4,
                     int vol4) {
    int i = blockIdx.x * blockDim.x + threadIdx.x;   // always < vol4 (exact grid)

    float4 m = mask4[i];
    float4* __restrict__ o = out4 + i;

#pragma unroll
    for (int c = 0; c < N_LABELS; c++) {
        const float lab = (float)(c + 1);
        float4 r;
        r.x = (m.x == lab) ? 1.0f : 0.0f;
        r.y = (m.y == lab) ? 1.0f : 0.0f;
        r.z = (m.z == lab) ? 1.0f : 0.0f;
        r.w = (m.w == lab) ? 1.0f : 0.0f;
        __stwt(&o[(size_t)c * (size_t)vol4], r);
    }
}

extern "C" void kernel_launch(void* const* d_in, const int* in_sizes, int n_in,
                              void* d_out, int out_size) {
    const float* mask = (const float*)d_in[0];
    float* out = (float*)d_out;

    int vol  = in_sizes[0];         // 256*256*48 = 3,145,728
    int vol4 = vol / 4;             // 786,432 = 3072 * 256 exactly

    onehot40_kernel<<<vol4 / 256, 256>>>(
        (const float4*)mask, (float4*)out, vol4);
}

// round 13
// speedup vs baseline: 1.0035x; 1.0035x over previous
#include <cuda_runtime.h>
#include <cuda_bf16.h>
#include <cstdint>

// One-hot expansion: mask [1,1,256,256,48] fp32 integer labels 0..40
//   -> out [1,40,256,256,48], out[:,c] = (mask == c+1) ? 1.0f : 0.0f
//
// FINAL (converged at the hardware write ceiling, ~5.8 TB/s):
//   - Store policy: plain evict-normal. Measured: evict-first neutral [R6],
//     write-through -2% [R10].
//   - Layout: thread t <-> float4 t; each warp STG.128 spans a contiguous
//     512B (4 full 128B lines). Per-thread-contiguous striding costs 2x L1
//     wavefronts per store [R2].
//   - Invariant to store MLP [R7], occupancy 52-88% [R6/R7], and write-stream
//     locality / channel-major ordering [R8].
//   - Byte floor: 503MB output + 12.6MB mask is mandatory; memset+scatter
//     alternatives cost MORE bytes (sector-granularity dirties).
// Exact grid (786,432 float4 = 3072 x 256): no bounds check; 40 constant-
// offset stores off one base pointer.

#define N_LABELS 40

__global__ __launch_bounds__(256)
void onehot40_kernel(const float4* __restrict__ mask4,
                     float4* __restrict__ out4,
                     int vol4) {
    int i = blockIdx.x * blockDim.x + threadIdx.x;   // always < vol4 (exact grid)

    float4 m = mask4[i];
    float4* __restrict__ o = out4 + i;

#pragma unroll
    for (int c = 0; c < N_LABELS; c++) {
        const float lab = (float)(c + 1);
        float4 r;
        r.x = (m.x == lab) ? 1.0f : 0.0f;
        r.y = (m.y == lab) ? 1.0f : 0.0f;
        r.z = (m.z == lab) ? 1.0f : 0.0f;
        r.w = (m.w == lab) ? 1.0f : 0.0f;
        o[(size_t)c * (size_t)vol4] = r;
    }
}

extern "C" void kernel_launch(void* const* d_in, const int* in_sizes, int n_in,
                              void* d_out, int out_size) {
    const float* mask = (const float*)d_in[0];
    float* out = (float*)d_out;

    int vol  = in_sizes[0];         // 256*256*48 = 3,145,728
    int vol4 = vol / 4;             // 786,432 = 3072 * 256 exactly

    onehot40_kernel<<<vol4 / 256, 256>>>(
        (const float4*)mask, (float4*)out, vol4);
}

// round 14
// speedup vs baseline: 1.0334x; 1.0297x over previous
#include <cuda_runtime.h>
#include <cuda_bf16.h>
#include <cstdint>

// One-hot expansion: mask [1,1,256,256,48] fp32 integer labels 0..40
//   -> out [1,40,256,256,48], out[:,c] = (mask == c+1) ? 1.0f : 0.0f
//
// Streaming-store bound (~5.8 TB/s plateau, invariant to L2 policy [R6/R10],
// store MLP [R7], occupancy [R6/R7], stream locality [R8]).
// This round: Blackwell 256-bit vector stores (st.global.v8.f32, PTX 8.7+,
// sm_100+). Each lane stores 32B; a warp store covers 1024B contiguous
// (8 full 128B lines per instruction) — halved store instruction count and
// store-queue entries per byte. Last untested mechanism.

#define N_LABELS 40

__device__ __forceinline__ void ldg256(const float* p, float4& a, float4& b) {
    asm volatile("ld.global.nc.v8.f32 {%0,%1,%2,%3,%4,%5,%6,%7}, [%8];"
        : "=f"(a.x), "=f"(a.y), "=f"(a.z), "=f"(a.w),
          "=f"(b.x), "=f"(b.y), "=f"(b.z), "=f"(b.w)
        : "l"(p));
}

__device__ __forceinline__ void stg256(float* p, const float4& a, const float4& b) {
    asm volatile("st.global.v8.f32 [%0], {%1,%2,%3,%4,%5,%6,%7,%8};"
        :: "l"(p),
           "f"(a.x), "f"(a.y), "f"(a.z), "f"(a.w),
           "f"(b.x), "f"(b.y), "f"(b.z), "f"(b.w)
        : "memory");
}

__global__ __launch_bounds__(256)
void onehot40_kernel(const float* __restrict__ mask,
                     float* __restrict__ out,
                     int vol) {
    // thread t owns the 8-float (32B) chunk t; lanes adjacent -> each warp
    // STG.256 spans a contiguous 1024B (8 full 128B lines).
    int i = blockIdx.x * blockDim.x + threadIdx.x;   // chunk index, exact grid
    const float* mp = mask + (size_t)i * 8;

    float4 ma, mb;
    ldg256(mp, ma, mb);

    float* o = out + (size_t)i * 8;

#pragma unroll
    for (int c = 0; c < N_LABELS; c++) {
        const float lab = (float)(c + 1);
        float4 ra, rb;
        ra.x = (ma.x == lab) ? 1.0f : 0.0f;
        ra.y = (ma.y == lab) ? 1.0f : 0.0f;
        ra.z = (ma.z == lab) ? 1.0f : 0.0f;
        ra.w = (ma.w == lab) ? 1.0f : 0.0f;
        rb.x = (mb.x == lab) ? 1.0f : 0.0f;
        rb.y = (mb.y == lab) ? 1.0f : 0.0f;
        rb.z = (mb.z == lab) ? 1.0f : 0.0f;
        rb.w = (mb.w == lab) ? 1.0f : 0.0f;
        stg256(o + (size_t)c * (size_t)vol, ra, rb);
    }
}

extern "C" void kernel_launch(void* const* d_in, const int* in_sizes, int n_in,
                              void* d_out, int out_size) {
    const float* mask = (const float*)d_in[0];
    float* out = (float*)d_out;

    int vol    = in_sizes[0];       // 256*256*48 = 3,145,728
    int chunks = vol / 8;           // 393,216 = 1536 * 256 exactly

    onehot40_kernel<<<chunks / 256, 256>>>(mask, out, vol);
}

// round 17
// speedup vs baseline: 1.0502x; 1.0163x over previous
#include <cuda_runtime.h>
#include <cuda_bf16.h>
#include <cstdint>

// One-hot expansion: mask [1,1,256,256,48] fp32 integer labels 0..40
//   -> out [1,40,256,256,48], out[:,c] = (mask == c+1) ? 1.0f : 0.0f
//
// FINAL FAMILY: streaming-store bound at the measured HBM write ceiling
// (~5.8 TB/s; invariant to L2 policy [R6/R10], store MLP [R7], occupancy
// [R6/R7/R14], stream locality [R8], 128b vs 256b stores [R14]).
// Best variant: Blackwell 256-bit stores (st.global.v8.f32) — warp store =
// 1024B contiguous (8 full 128B lines/instr). This round only reshapes the
// wave structure: block=128, grid=3072 (identical warp-level access pattern,
// smoother scheduling / smaller tail).

#define N_LABELS 40

__device__ __forceinline__ void ldg256(const float* p, float4& a, float4& b) {
    asm volatile("ld.global.nc.v8.f32 {%0,%1,%2,%3,%4,%5,%6,%7}, [%8];"
        : "=f"(a.x), "=f"(a.y), "=f"(a.z), "=f"(a.w),
          "=f"(b.x), "=f"(b.y), "=f"(b.z), "=f"(b.w)
        : "l"(p));
}

__device__ __forceinline__ void stg256(float* p, const float4& a, const float4& b) {
    asm volatile("st.global.v8.f32 [%0], {%1,%2,%3,%4,%5,%6,%7,%8};"
        :: "l"(p),
           "f"(a.x), "f"(a.y), "f"(a.z), "f"(a.w),
           "f"(b.x), "f"(b.y), "f"(b.z), "f"(b.w)
        : "memory");
}

__global__ __launch_bounds__(128)
void onehot40_kernel(const float* __restrict__ mask,
                     float* __restrict__ out,
                     int vol) {
    // thread t owns 8-float (32B) chunk t; lanes adjacent -> each warp
    // STG.256 spans a contiguous 1024B (8 full 128B lines). Exact grid.
    int i = blockIdx.x * blockDim.x + threadIdx.x;
    const float* mp = mask + (size_t)i * 8;

    float4 ma, mb;
    ldg256(mp, ma, mb);

    float* o = out + (size_t)i * 8;

#pragma unroll
    for (int c = 0; c < N_LABELS; c++) {
        const float lab = (float)(c + 1);
        float4 ra, rb;
        ra.x = (ma.x == lab) ? 1.0f : 0.0f;
        ra.y = (ma.y == lab) ? 1.0f : 0.0f;
        ra.z = (ma.z == lab) ? 1.0f : 0.0f;
        ra.w = (ma.w == lab) ? 1.0f : 0.0f;
        rb.x = (mb.x == lab) ? 1.0f : 0.0f;
        rb.y = (mb.y == lab) ? 1.0f : 0.0f;
        rb.z = (mb.z == lab) ? 1.0f : 0.0f;
        rb.w = (mb.w == lab) ? 1.0f : 0.0f;
        stg256(o + (size_t)c * (size_t)vol, ra, rb);
    }
}

extern "C" void kernel_launch(void* const* d_in, const int* in_sizes, int n_in,
                              void* d_out, int out_size) {
    const float* mask = (const float*)d_in[0];
    float* out = (float*)d_out;

    int vol    = in_sizes[0];       // 256*256*48 = 3,145,728
    int chunks = vol / 8;           // 393,216 = 3072 * 128 exactly

    onehot40_kernel<<<chunks / 128, 128>>>(mask, out, vol);
}